// round 1
// baseline (speedup 1.0000x reference)
#include <cuda_runtime.h>
#include <math.h>

#define NSH 49
#define CC  128
#define HH  256
#define GP  182
#define PCH 26
#define EPSV 1e-5f
#define WPAD 129

// shared memory layout (floats):
// xn    : 0     .. 6272
// hbuf  : 6272  .. +12544
// htbf  : 18816 .. +12544
// wst   : 31360 .. +16512   (also aliased as gbuf: 26*256 = 6656)
// tgc   : 47872 .. +1274
// fgc   : 49146 .. +1274
// sgate : 50420 .. +256
// rbuf  : 50676 .. +32
#define SMEM_FLOATS 50708

__constant__ int c_ltab[NSH] = {
    0,
    1,1,1,
    2,2,2,2,2,
    3,3,3,3,3,3,3,
    4,4,4,4,4,4,4,4,4,
    5,5,5,5,5,5,5,5,5,5,5,
    6,6,6,6,6,6,6,6,6,6,6,6,6};

// bal[m] = 1 / (6*(2l+1)), m>=1
__constant__ float c_bal[NSH] = {
    0.0f,
    0.05555555556f,0.05555555556f,0.05555555556f,
    0.03333333333f,0.03333333333f,0.03333333333f,0.03333333333f,0.03333333333f,
    0.02380952381f,0.02380952381f,0.02380952381f,0.02380952381f,0.02380952381f,0.02380952381f,0.02380952381f,
    0.01851851852f,0.01851851852f,0.01851851852f,0.01851851852f,0.01851851852f,0.01851851852f,0.01851851852f,0.01851851852f,0.01851851852f,
    0.01515151515f,0.01515151515f,0.01515151515f,0.01515151515f,0.01515151515f,0.01515151515f,0.01515151515f,0.01515151515f,0.01515151515f,0.01515151515f,0.01515151515f,
    0.01282051282f,0.01282051282f,0.01282051282f,0.01282051282f,0.01282051282f,0.01282051282f,0.01282051282f,0.01282051282f,0.01282051282f,0.01282051282f,0.01282051282f,0.01282051282f,0.01282051282f};

__device__ __forceinline__ float fast_silu(float v) {
    return __fdividef(v, 1.0f + __expf(-v));
}

// Thread owns two output columns (wa, wb) and CNT rows of the activation.
template<int CNT>
__device__ __forceinline__ void dot2(const float* __restrict__ wa,
                                     const float* __restrict__ wb,
                                     const float* __restrict__ xr,
                                     int rstride, int K,
                                     float* __restrict__ accA,
                                     float* __restrict__ accB)
{
    #pragma unroll 4
    for (int c = 0; c < K; c++) {
        float a = wa[c];
        float b = wb[c];
        #pragma unroll
        for (int k = 0; k < CNT; k++) {
            float xv = xr[k * rstride + c];   // warp-uniform -> smem broadcast
            accA[k] = fmaf(a, xv, accA[k]);
            accB[k] = fmaf(b, xv, accB[k]);
        }
    }
}

__device__ __forceinline__ void dot2_dispatch(int cnt,
                                              const float* wa, const float* wb,
                                              const float* xr, int rstride, int K,
                                              float* accA, float* accB)
{
    switch (cnt) {
        case 1: dot2<1>(wa, wb, xr, rstride, K, accA, accB); break;
        case 2: dot2<2>(wa, wb, xr, rstride, K, accA, accB); break;
        case 3: dot2<3>(wa, wb, xr, rstride, K, accA, accB); break;
        case 4: dot2<4>(wa, wb, xr, rstride, K, accA, accB); break;
        default: break;
    }
}

template<int KC>
__device__ __forceinline__ void grid_fwd(const float* __restrict__ hb,
                                         const float* __restrict__ tg,
                                         int psel, int o4, float4* __restrict__ acc)
{
    for (int i = 0; i < NSH; i++) {
        float4 hv = *reinterpret_cast<const float4*>(hb + i * HH + o4);
        #pragma unroll
        for (int k = 0; k < KC; k++) {
            float t = tg[(psel + 4 * k) * NSH + i];   // warp-uniform broadcast
            acc[k].x = fmaf(t, hv.x, acc[k].x);
            acc[k].y = fmaf(t, hv.y, acc[k].y);
            acc[k].z = fmaf(t, hv.z, acc[k].z);
            acc[k].w = fmaf(t, hv.w, acc[k].w);
        }
    }
}

__global__ void __launch_bounds__(256, 1)
ffn_fused(const float* __restrict__ x,
          const float* __restrict__ ln0_w, const float* __restrict__ ln0_b,
          const float* __restrict__ aff_w,
          const float* __restrict__ w1, const float* __restrict__ b1,
          const float* __restrict__ gate_w, const float* __restrict__ gate_b,
          const float* __restrict__ w2, const float* __restrict__ b2,
          const float* __restrict__ to_grid, const float* __restrict__ from_grid,
          float* __restrict__ out)
{
    extern __shared__ float sm[];
    float* xn    = sm;
    float* hbuf  = sm + 6272;
    float* htbf  = hbuf + 12544;
    float* wst   = htbf + 12544;
    float* tgc   = wst + 16512;
    float* fgc   = tgc + 1274;
    float* sgate = fgc + 1274;
    float* rbuf  = sgate + 256;

    const int tid = threadIdx.x;
    const int n   = blockIdx.x;
    const int wid = tid >> 5;
    const int lid = tid & 31;

    // ---------------- Phase A: load + norms ----------------
    const float4* xin = reinterpret_cast<const float4*>(x + (size_t)n * (NSH * CC));
    float4* xns = reinterpret_cast<float4*>(xn);
    for (int j = tid; j < NSH * CC / 4; j += 256) xns[j] = xin[j];
    __syncthreads();

    float s0 = 0.f, q0 = 0.f, sw = 0.f;
    for (int j = tid; j < NSH * CC; j += 256) {
        float v = xn[j];
        int m = j >> 7;
        if (m == 0) { s0 += v; q0 += v * v; }
        else        sw += c_bal[m] * v * v;
    }
    #pragma unroll
    for (int o = 16; o > 0; o >>= 1) {
        s0 += __shfl_xor_sync(0xffffffffu, s0, o);
        q0 += __shfl_xor_sync(0xffffffffu, q0, o);
        sw += __shfl_xor_sync(0xffffffffu, sw, o);
    }
    if (lid == 0) { rbuf[wid] = s0; rbuf[8 + wid] = q0; rbuf[16 + wid] = sw; }
    __syncthreads();
    if (tid == 0) {
        float a = 0.f, b = 0.f, c = 0.f;
        #pragma unroll
        for (int k = 0; k < 8; k++) { a += rbuf[k]; b += rbuf[8 + k]; c += rbuf[16 + k]; }
        float muv  = a * (1.0f / CC);
        float varv = b * (1.0f / CC) - muv * muv;
        rbuf[24] = muv;
        rbuf[25] = rsqrtf(varv + EPSV);
        rbuf[26] = rsqrtf(c * (1.0f / CC) + EPSV);
    }
    __syncthreads();
    const float mu = rbuf[24], rstd = rbuf[25], inv = rbuf[26];

    for (int j = tid; j < NSH * CC; j += 256) {
        int m = j >> 7, c = j & 127;
        float v = xn[j];
        if (m == 0) v = (v - mu) * rstd * ln0_w[c] + ln0_b[c];
        else        v = v * inv * aff_w[(c_ltab[m] - 1) * CC + c];
        xn[j] = v;
    }
    for (int j = tid; j < NSH * HH; j += 256) htbf[j] = 0.f;
    __syncthreads();

    // ---------------- Phase B: gate = silu(xn0 @ gate_w^T + gate_b) ----------------
    for (int ho = wid; ho < HH; ho += 8) {
        const float* gw = gate_w + ho * CC;
        float p = gw[lid]      * xn[lid]
                + gw[lid + 32] * xn[lid + 32]
                + gw[lid + 64] * xn[lid + 64]
                + gw[lid + 96] * xn[lid + 96];
        #pragma unroll
        for (int o = 16; o > 0; o >>= 1) p += __shfl_xor_sync(0xffffffffu, p, o);
        if (lid == 0) sgate[ho] = fast_silu(p + gate_b[ho]);
    }

    // ---------------- Phase C: h[m,:] = xn[m,:] @ w1[l]^T (+b1 on m==0) ----------------
    const int oc  = tid & 63;
    const int mse = tid >> 6;
    for (int l = 0; l <= 6; l++) {
        const int g = 2 * l + 1, mbase = l * l;
        const int cnt = (g - mse + 3) >> 2;
        for (int hf = 0; hf < 2; hf++) {
            __syncthreads();
            const float4* ws4 = reinterpret_cast<const float4*>(w1 + ((size_t)l * HH + hf * 128) * CC);
            for (int j4 = tid; j4 < 128 * CC / 4; j4 += 256) {
                float4 v = ws4[j4];
                int j = j4 * 4;
                int o = j >> 7, c = j & 127;
                float* d = wst + o * WPAD + c;
                d[0] = v.x; d[1] = v.y; d[2] = v.z; d[3] = v.w;
            }
            __syncthreads();
            if (cnt > 0) {
                float accA[4] = {0, 0, 0, 0}, accB[4] = {0, 0, 0, 0};
                dot2_dispatch(cnt, wst + oc * WPAD, wst + (oc + 64) * WPAD,
                              xn + (mbase + mse) * CC, 4 * CC, CC, accA, accB);
                for (int k = 0; k < cnt; k++) {
                    int m = mbase + mse + 4 * k;
                    float a = accA[k], b = accB[k];
                    if (m == 0) { a += b1[hf * 128 + oc]; b += b1[hf * 128 + oc + 64]; }
                    hbuf[m * HH + hf * 128 + oc]      = a;
                    hbuf[m * HH + hf * 128 + oc + 64] = b;
                }
            }
        }
    }

    // ---------------- Phase D: ht = from_grid^T @ silu(to_grid @ h) ----------------
    float* gbuf = wst;                 // alias: 26*256 floats
    const int o4   = (tid & 63) * 4;
    const int psel = tid >> 6;
    for (int ch = 0; ch < 7; ch++) {
        const int pbase = ch * PCH;
        __syncthreads();
        for (int j = tid; j < PCH * NSH; j += 256) {
            tgc[j] = to_grid[pbase * NSH + j];
            fgc[j] = from_grid[pbase * NSH + j];
        }
        __syncthreads();
        {
            float4 acc[7];
            const int kcnt = (psel < 2) ? 7 : 6;
            #pragma unroll
            for (int k = 0; k < 7; k++) acc[k] = make_float4(0.f, 0.f, 0.f, 0.f);
            if (psel < 2) grid_fwd<7>(hbuf, tgc, psel, o4, acc);
            else          grid_fwd<6>(hbuf, tgc, psel, o4, acc);
            for (int k = 0; k < kcnt; k++) {
                int p = psel + 4 * k;
                float4 v = acc[k];
                v.x = fast_silu(v.x); v.y = fast_silu(v.y);
                v.z = fast_silu(v.z); v.w = fast_silu(v.w);
                *reinterpret_cast<float4*>(gbuf + p * HH + o4) = v;
            }
        }
        __syncthreads();
        for (int i = psel; i < NSH; i += 4) {
            float4 a = *reinterpret_cast<float4*>(htbf + i * HH + o4);
            #pragma unroll
            for (int p = 0; p < PCH; p++) {
                float f = fgc[p * NSH + i];
                float4 gv = *reinterpret_cast<const float4*>(gbuf + p * HH + o4);
                a.x = fmaf(f, gv.x, a.x);
                a.y = fmaf(f, gv.y, a.y);
                a.z = fmaf(f, gv.z, a.z);
                a.w = fmaf(f, gv.w, a.w);
            }
            *reinterpret_cast<float4*>(htbf + i * HH + o4) = a;
        }
    }

    // ---------------- Phase E: out[m,:] = h2[m,:] @ w2[l]^T (+b2 on m==0) ----------------
    float* outn = out + (size_t)n * (NSH * CC);
    for (int l = 0; l <= 6; l++) {
        const int g = 2 * l + 1, mbase = l * l;
        const int cnt = (g - mse + 3) >> 2;
        float accA[4] = {0, 0, 0, 0}, accB[4] = {0, 0, 0, 0};
        for (int ih = 0; ih < 2; ih++) {
            __syncthreads();
            const float* wsrc = w2 + (size_t)l * CC * HH + ih * 128;
            for (int j4 = tid; j4 < 128 * 128 / 4; j4 += 256) {
                int j = j4 * 4;
                int o = j >> 7, ii = j & 127;
                const float4 v = *reinterpret_cast<const float4*>(wsrc + o * HH + ii);
                float* d = wst + o * WPAD + ii;
                d[0] = v.x; d[1] = v.y; d[2] = v.z; d[3] = v.w;
            }
            __syncthreads();
            if (cnt > 0) {
                const float* rows = (l == 0) ? (sgate + ih * 128)
                                             : (htbf + (mbase + mse) * HH + ih * 128);
                dot2_dispatch(cnt, wst + oc * WPAD, wst + (oc + 64) * WPAD,
                              rows, 4 * HH, 128, accA, accB);
            }
        }
        if (cnt > 0) {
            for (int k = 0; k < cnt; k++) {
                int m = mbase + mse + 4 * k;
                float a = accA[k], b = accB[k];
                if (m == 0) { a += b2[oc]; b += b2[oc + 64]; }
                outn[m * CC + oc]      = a;
                outn[m * CC + oc + 64] = b;
            }
        }
    }
}

extern "C" void kernel_launch(void* const* d_in, const int* in_sizes, int n_in,
                              void* d_out, int out_size)
{
    const float* x      = (const float*)d_in[0];
    const float* ln0_w  = (const float*)d_in[1];
    const float* ln0_b  = (const float*)d_in[2];
    const float* aff_w  = (const float*)d_in[3];
    const float* w1     = (const float*)d_in[4];
    const float* b1     = (const float*)d_in[5];
    const float* gate_w = (const float*)d_in[6];
    const float* gate_b = (const float*)d_in[7];
    const float* w2     = (const float*)d_in[8];
    const float* b2     = (const float*)d_in[9];
    const float* tg     = (const float*)d_in[10];
    const float* fg     = (const float*)d_in[11];
    float* out = (float*)d_out;

    const int n_nodes = in_sizes[0] / (NSH * CC);
    const int smem_bytes = SMEM_FLOATS * (int)sizeof(float);
    cudaFuncSetAttribute(ffn_fused, cudaFuncAttributeMaxDynamicSharedMemorySize, smem_bytes);
    ffn_fused<<<n_nodes, 256, smem_bytes>>>(x, ln0_w, ln0_b, aff_w, w1, b1,
                                            gate_w, gate_b, w2, b2, tg, fg, out);
}

// round 3
// speedup vs baseline: 1.5479x; 1.5479x over previous
#include <cuda_runtime.h>
#include <math.h>

#define NSH 49
#define CC  128
#define HH  256
#define EPSV 1e-5f
#define WPAD 132     // multiple of 4 -> float4 STS/LDS, conflict-free for lane-stride access
#define PPAD 28      // padded p-dimension per chunk (26 real + 2 zero)

// smem layout (floats) — every base offset is a multiple of 4 (16B-aligned for LDS.128)
#define O_XN    0
#define O_HBUF  6272
#define O_HTBF  18816
#define O_WST   31360          // 128*132 = 16896 ; aliased as gbuf (28*256=7168)
#define O_TGC   48256          // 26*49 = 1274, padded to 1276
#define O_FGCT  49532          // 49*28 = 1372 (transposed, padded) — 16B aligned
#define O_SGATE 50904          // 256 — 16B aligned
#define O_RBUF  51160
#define SMEM_FLOATS 51192

__constant__ int c_ltab[NSH] = {
    0,
    1,1,1,
    2,2,2,2,2,
    3,3,3,3,3,3,3,
    4,4,4,4,4,4,4,4,4,
    5,5,5,5,5,5,5,5,5,5,5,
    6,6,6,6,6,6,6,6,6,6,6,6,6};

__constant__ float c_bal[NSH] = {
    0.0f,
    0.05555555556f,0.05555555556f,0.05555555556f,
    0.03333333333f,0.03333333333f,0.03333333333f,0.03333333333f,0.03333333333f,
    0.02380952381f,0.02380952381f,0.02380952381f,0.02380952381f,0.02380952381f,0.02380952381f,0.02380952381f,
    0.01851851852f,0.01851851852f,0.01851851852f,0.01851851852f,0.01851851852f,0.01851851852f,0.01851851852f,0.01851851852f,0.01851851852f,
    0.01515151515f,0.01515151515f,0.01515151515f,0.01515151515f,0.01515151515f,0.01515151515f,0.01515151515f,0.01515151515f,0.01515151515f,0.01515151515f,0.01515151515f,
    0.01282051282f,0.01282051282f,0.01282051282f,0.01282051282f,0.01282051282f,0.01282051282f,0.01282051282f,0.01282051282f,0.01282051282f,0.01282051282f,0.01282051282f,0.01282051282f,0.01282051282f};

__device__ __forceinline__ float fast_silu(float v) {
    return __fdividef(v, 1.0f + __expf(-v));
}

// Stage a 128x128 weight block (row-major, row stride srcstride) into wst with
// pad-132 rows. float4 throughout: 4 wf per warp-iter, fully coalesced LDG.
__device__ __forceinline__ void stage_w(float* __restrict__ wst,
                                        const float* __restrict__ src,
                                        int srcstride, int tid)
{
    #pragma unroll 4
    for (int j4 = tid; j4 < 4096; j4 += 256) {
        int o  = j4 >> 5;
        int c4 = (j4 & 31) << 2;
        *reinterpret_cast<float4*>(wst + o * WPAD + c4) =
            *reinterpret_cast<const float4*>(src + o * srcstride + c4);
    }
}

// Thread owns one weight column (128 K), CNT activation rows (stride xstride).
// Per c4: 1 LDS.128 weight (conflict-free) + CNT LDS.128 broadcasts, 4*CNT FMA.
template<int CNT>
__device__ __forceinline__ void dotc(const float* __restrict__ wcol,
                                     const float* __restrict__ xbase,
                                     int xstride, float* __restrict__ acc)
{
    #pragma unroll 4
    for (int c4 = 0; c4 < CC; c4 += 4) {
        float4 w = *reinterpret_cast<const float4*>(wcol + c4);
        #pragma unroll
        for (int k = 0; k < CNT; k++) {
            float4 xv = *reinterpret_cast<const float4*>(xbase + k * xstride + c4);
            acc[k] = fmaf(w.x, xv.x, acc[k]);
            acc[k] = fmaf(w.y, xv.y, acc[k]);
            acc[k] = fmaf(w.z, xv.z, acc[k]);
            acc[k] = fmaf(w.w, xv.w, acc[k]);
        }
    }
}

__device__ __forceinline__ void dotc_dispatch(int cnt, const float* wcol,
                                              const float* xbase, int xstride,
                                              float* acc)
{
    switch (cnt) {
        case 1: dotc<1>(wcol, xbase, xstride, acc); break;
        case 2: dotc<2>(wcol, xbase, xstride, acc); break;
        case 3: dotc<3>(wcol, xbase, xstride, acc); break;
        case 4: dotc<4>(wcol, xbase, xstride, acc); break;
        case 5: dotc<5>(wcol, xbase, xstride, acc); break;
        case 6: dotc<6>(wcol, xbase, xstride, acc); break;
        case 7: dotc<7>(wcol, xbase, xstride, acc); break;
        default: break;
    }
}

// Grid forward: thread owns o4 (4 channels), p = psel+4k. Per i: 1 LDS.128 + KC bcast.
template<int KC>
__device__ __forceinline__ void fwd_grid(const float* __restrict__ hb,
                                         const float* __restrict__ tg,
                                         int psel, int o4, float4* __restrict__ acc)
{
    #pragma unroll 7
    for (int i = 0; i < NSH; i++) {
        float4 hv = *reinterpret_cast<const float4*>(hb + i * HH + o4);
        #pragma unroll
        for (int k = 0; k < KC; k++) {
            float t = tg[(psel + 4 * k) * NSH + i];
            acc[k].x = fmaf(t, hv.x, acc[k].x);
            acc[k].y = fmaf(t, hv.y, acc[k].y);
            acc[k].z = fmaf(t, hv.z, acc[k].z);
            acc[k].w = fmaf(t, hv.w, acc[k].w);
        }
    }
}

// Grid backward: thread owns o4 and KI rows i = isel+4k; ht accumulators live in
// registers across the whole phase. p streamed in blocks of 4 (f as float4 bcast).
template<int KI>
__device__ __forceinline__ void bwd_grid(const float* __restrict__ gb,
                                         const float* __restrict__ fgT,
                                         int isel, int o4, float4* __restrict__ acc)
{
    #pragma unroll 1
    for (int pb = 0; pb < PPAD; pb += 4) {
        float4 g0 = *reinterpret_cast<const float4*>(gb + (pb + 0) * HH + o4);
        float4 g1 = *reinterpret_cast<const float4*>(gb + (pb + 1) * HH + o4);
        float4 g2 = *reinterpret_cast<const float4*>(gb + (pb + 2) * HH + o4);
        float4 g3 = *reinterpret_cast<const float4*>(gb + (pb + 3) * HH + o4);
        #pragma unroll
        for (int k = 0; k < KI; k++) {
            float4 f = *reinterpret_cast<const float4*>(fgT + (isel + 4 * k) * PPAD + pb);
            acc[k].x = fmaf(f.x, g0.x, acc[k].x);
            acc[k].y = fmaf(f.x, g0.y, acc[k].y);
            acc[k].z = fmaf(f.x, g0.z, acc[k].z);
            acc[k].w = fmaf(f.x, g0.w, acc[k].w);
            acc[k].x = fmaf(f.y, g1.x, acc[k].x);
            acc[k].y = fmaf(f.y, g1.y, acc[k].y);
            acc[k].z = fmaf(f.y, g1.z, acc[k].z);
            acc[k].w = fmaf(f.y, g1.w, acc[k].w);
            acc[k].x = fmaf(f.z, g2.x, acc[k].x);
            acc[k].y = fmaf(f.z, g2.y, acc[k].y);
            acc[k].z = fmaf(f.z, g2.z, acc[k].z);
            acc[k].w = fmaf(f.z, g2.w, acc[k].w);
            acc[k].x = fmaf(f.w, g3.x, acc[k].x);
            acc[k].y = fmaf(f.w, g3.y, acc[k].y);
            acc[k].z = fmaf(f.w, g3.z, acc[k].z);
            acc[k].w = fmaf(f.w, g3.w, acc[k].w);
        }
    }
}

__global__ void __launch_bounds__(256, 1)
ffn_fused(const float* __restrict__ x,
          const float* __restrict__ ln0_w, const float* __restrict__ ln0_b,
          const float* __restrict__ aff_w,
          const float* __restrict__ w1, const float* __restrict__ b1,
          const float* __restrict__ gate_w, const float* __restrict__ gate_b,
          const float* __restrict__ w2, const float* __restrict__ b2,
          const float* __restrict__ to_grid, const float* __restrict__ from_grid,
          float* __restrict__ out)
{
    extern __shared__ float sm[];
    float* xn    = sm + O_XN;
    float* hbuf  = sm + O_HBUF;
    float* htbf  = sm + O_HTBF;
    float* wst   = sm + O_WST;
    float* tgc   = sm + O_TGC;
    float* fgcT  = sm + O_FGCT;
    float* sgate = sm + O_SGATE;
    float* rbuf  = sm + O_RBUF;

    const int tid = threadIdx.x;
    const int n   = blockIdx.x;
    const int wid = tid >> 5;
    const int lid = tid & 31;

    // ---------------- Phase A: load + norms (all float4) ----------------
    const float4* xin = reinterpret_cast<const float4*>(x + (size_t)n * (NSH * CC));
    float4* xns = reinterpret_cast<float4*>(xn);
    #pragma unroll 4
    for (int j4 = tid; j4 < NSH * CC / 4; j4 += 256) xns[j4] = xin[j4];
    __syncthreads();

    float s0 = 0.f, q0 = 0.f, sw = 0.f;
    #pragma unroll 4
    for (int j4 = tid; j4 < NSH * CC / 4; j4 += 256) {
        float4 v = xns[j4];
        int m = j4 >> 5;
        float d = v.x * v.x + v.y * v.y + v.z * v.z + v.w * v.w;
        if (m == 0) { s0 += v.x + v.y + v.z + v.w; q0 += d; }
        else        sw += c_bal[m] * d;
    }
    #pragma unroll
    for (int o = 16; o > 0; o >>= 1) {
        s0 += __shfl_xor_sync(0xffffffffu, s0, o);
        q0 += __shfl_xor_sync(0xffffffffu, q0, o);
        sw += __shfl_xor_sync(0xffffffffu, sw, o);
    }
    if (lid == 0) { rbuf[wid] = s0; rbuf[8 + wid] = q0; rbuf[16 + wid] = sw; }
    __syncthreads();
    if (tid == 0) {
        float a = 0.f, b = 0.f, c = 0.f;
        #pragma unroll
        for (int k = 0; k < 8; k++) { a += rbuf[k]; b += rbuf[8 + k]; c += rbuf[16 + k]; }
        float muv  = a * (1.0f / CC);
        float varv = b * (1.0f / CC) - muv * muv;
        rbuf[24] = muv;
        rbuf[25] = rsqrtf(varv + EPSV);
        rbuf[26] = rsqrtf(c * (1.0f / CC) + EPSV);
    }
    __syncthreads();
    const float mu = rbuf[24], rstd = rbuf[25], inv = rbuf[26];

    #pragma unroll 4
    for (int j4 = tid; j4 < NSH * CC / 4; j4 += 256) {
        int m = j4 >> 5, c4 = (j4 & 31) << 2;
        float4 v = xns[j4];
        if (m == 0) {
            float4 w = *reinterpret_cast<const float4*>(ln0_w + c4);
            float4 b = *reinterpret_cast<const float4*>(ln0_b + c4);
            v.x = (v.x - mu) * rstd * w.x + b.x;
            v.y = (v.y - mu) * rstd * w.y + b.y;
            v.z = (v.z - mu) * rstd * w.z + b.z;
            v.w = (v.w - mu) * rstd * w.w + b.w;
        } else {
            float4 a = *reinterpret_cast<const float4*>(aff_w + (c_ltab[m] - 1) * CC + c4);
            v.x *= inv * a.x; v.y *= inv * a.y; v.z *= inv * a.z; v.w *= inv * a.w;
        }
        xns[j4] = v;
    }
    __syncthreads();

    // ---------------- Phase B: gate = silu(xn0 @ gate_w^T + gate_b) ----------------
    {
        const int c4 = lid << 2;
        float4 x0 = *reinterpret_cast<const float4*>(xn + c4);
        for (int ho = wid; ho < HH; ho += 8) {
            float4 g = *reinterpret_cast<const float4*>(gate_w + ho * CC + c4);
            float p = g.x * x0.x + g.y * x0.y + g.z * x0.z + g.w * x0.w;
            #pragma unroll
            for (int o = 16; o > 0; o >>= 1) p += __shfl_xor_sync(0xffffffffu, p, o);
            if (lid == 0) sgate[ho] = fast_silu(p + gate_b[ho]);
        }
    }

    // ---------------- Phase C: h[m,:] = xn[m,:] @ w1[l]^T (+b1 on m==0) ----------------
    const int oc = tid & 127;       // output column within current 128-half
    const int rh = tid >> 7;        // row-half: rows rh, rh+2, ...
    for (int l = 0; l <= 6; l++) {
        const int g = 2 * l + 1, mbase = l * l;
        const int cnt = (g - rh + 1) >> 1;
        for (int hf = 0; hf < 2; hf++) {
            __syncthreads();
            stage_w(wst, w1 + (size_t)l * HH * CC + hf * 128 * CC, CC, tid);
            __syncthreads();
            if (cnt > 0) {
                float acc[7] = {0, 0, 0, 0, 0, 0, 0};
                dotc_dispatch(cnt, wst + oc * WPAD,
                              xn + (mbase + rh) * CC, 2 * CC, acc);
                #pragma unroll
                for (int k = 0; k < 7; k++) {
                    if (k < cnt) {
                        int m = mbase + rh + 2 * k;
                        float v = acc[k];
                        if (m == 0) v += b1[hf * 128 + oc];
                        hbuf[m * HH + hf * 128 + oc] = v;
                    }
                }
            }
        }
    }
    __syncthreads();

    // ---------------- Phase D: ht = from_grid^T @ silu(to_grid @ h) ----------------
    float* gbuf = wst;                     // 28 x 256 alias
    const int o4   = (tid & 63) << 2;
    const int psel = tid >> 6;             // also isel for backward
    // zero gbuf pad rows (26,27) and fgcT pad cols once
    for (int j = tid; j < 2 * HH; j += 256) gbuf[26 * HH + j] = 0.f;
    for (int i = tid; i < NSH; i += 256) {
        fgcT[i * PPAD + 26] = 0.f; fgcT[i * PPAD + 27] = 0.f;
    }

    const int KI = (psel == 0) ? 13 : 12;  // i = psel + 4k
    float4 hacc[13];
    #pragma unroll
    for (int k = 0; k < 13; k++) hacc[k] = make_float4(0.f, 0.f, 0.f, 0.f);

    for (int ch = 0; ch < 7; ch++) {
        const int pbase = ch * 26;
        __syncthreads();   // prev chunk's bwd reads of gbuf/fgcT done
        #pragma unroll 2
        for (int j = tid; j < 26 * NSH; j += 256) {
            int p = j / NSH, i = j - p * NSH;
            tgc[j] = to_grid[(size_t)(pbase + p) * NSH + i];
            fgcT[i * PPAD + p] = from_grid[(size_t)(pbase + p) * NSH + i];
        }
        __syncthreads();
        {
            float4 acc[7];
            const int kcnt = (psel < 2) ? 7 : 6;
            #pragma unroll
            for (int k = 0; k < 7; k++) acc[k] = make_float4(0.f, 0.f, 0.f, 0.f);
            if (psel < 2) fwd_grid<7>(hbuf, tgc, psel, o4, acc);
            else          fwd_grid<6>(hbuf, tgc, psel, o4, acc);
            #pragma unroll
            for (int k = 0; k < 7; k++) {
                if (k < kcnt) {
                    float4 v = acc[k];
                    v.x = fast_silu(v.x); v.y = fast_silu(v.y);
                    v.z = fast_silu(v.z); v.w = fast_silu(v.w);
                    *reinterpret_cast<float4*>(gbuf + (psel + 4 * k) * HH + o4) = v;
                }
            }
        }
        __syncthreads();
        if (psel == 0) bwd_grid<13>(gbuf, fgcT, psel, o4, hacc);
        else           bwd_grid<12>(gbuf, fgcT, psel, o4, hacc);
    }
    // write ht once
    #pragma unroll
    for (int k = 0; k < 13; k++) {
        if (k < KI)
            *reinterpret_cast<float4*>(htbf + (psel + 4 * k) * HH + o4) = hacc[k];
    }

    // ---------------- Phase E: out[m,:] = h2[m,:] @ w2[l]^T (+b2 on m==0) ----------------
    float* outn = out + (size_t)n * (NSH * CC);
    for (int l = 0; l <= 6; l++) {
        const int g = 2 * l + 1, mbase = l * l;
        const int cnt = (g - rh + 1) >> 1;
        float acc[7] = {0, 0, 0, 0, 0, 0, 0};
        for (int ih = 0; ih < 2; ih++) {
            __syncthreads();
            stage_w(wst, w2 + (size_t)l * CC * HH + ih * 128, HH, tid);
            __syncthreads();
            if (cnt > 0) {
                const float* rows = (l == 0) ? (sgate + ih * 128)
                                             : (htbf + (mbase + rh) * HH + ih * 128);
                dotc_dispatch(cnt, wst + oc * WPAD, rows, 2 * HH, acc);
            }
        }
        if (cnt > 0) {
            #pragma unroll
            for (int k = 0; k < 7; k++) {
                if (k < cnt) {
                    int m = mbase + rh + 2 * k;
                    float v = acc[k];
                    if (m == 0) v += b2[oc];
                    outn[m * CC + oc] = v;
                }
            }
        }
    }
}

extern "C" void kernel_launch(void* const* d_in, const int* in_sizes, int n_in,
                              void* d_out, int out_size)
{
    const float* x      = (const float*)d_in[0];
    const float* ln0_w  = (const float*)d_in[1];
    const float* ln0_b  = (const float*)d_in[2];
    const float* aff_w  = (const float*)d_in[3];
    const float* w1     = (const float*)d_in[4];
    const float* b1     = (const float*)d_in[5];
    const float* gate_w = (const float*)d_in[6];
    const float* gate_b = (const float*)d_in[7];
    const float* w2     = (const float*)d_in[8];
    const float* b2     = (const float*)d_in[9];
    const float* tg     = (const float*)d_in[10];
    const float* fg     = (const float*)d_in[11];
    float* out = (float*)d_out;

    const int n_nodes = in_sizes[0] / (NSH * CC);
    const int smem_bytes = SMEM_FLOATS * (int)sizeof(float);
    cudaFuncSetAttribute(ffn_fused, cudaFuncAttributeMaxDynamicSharedMemorySize, smem_bytes);
    ffn_fused<<<n_nodes, 256, smem_bytes>>>(x, ln0_w, ln0_b, aff_w, w1, b1,
                                            gate_w, gate_b, w2, b2, tg, fg, out);
}

// round 4
// speedup vs baseline: 1.6877x; 1.0904x over previous
#include <cuda_runtime.h>
#include <math.h>

#define NSH  49
#define CC   128
#define HH   256
#define EPSV 1e-5f
#define HPAD 52      // hbuf rows padded (49 real + 3 zero)
#define TGS  52      // tgc row stride (49 real + 3 zero)
#define PPAD 28      // padded grid-point dim per chunk (26 real + 2 zero)
#define WCPAD 132    // C weight row stride (128 K + pad)
#define WEPAD 260    // E weight row stride (256 K + pad)

// smem layout (floats), all bases multiple of 4 (16B aligned):
// xn    : 0      .. +6272   (49x128)     [E: reduction scratch]
// hbuf  : 6272   .. +13312  (52x256)     [after D: htbf 49x256]
// S     : 19584  .. +33792  scratch:
//     C: wstC = S (256x132 = 33792)
//     D: gbuf = S (28x256=7168); tgc = S+7168 (26x52=1352); fgcT = S+8520 (49x28=1372)
//     E: wstE = S (128x260 = 33280)
// sgate : 53376 .. +256
// rbuf  : 53632 .. +32
#define O_XN    0
#define O_HBUF  6272
#define O_S     19584
#define O_SGATE 53376
#define O_RBUF  53632
#define SMEM_FLOATS 53664

__constant__ int c_ltab[NSH] = {
    0,
    1,1,1,
    2,2,2,2,2,
    3,3,3,3,3,3,3,
    4,4,4,4,4,4,4,4,4,
    5,5,5,5,5,5,5,5,5,5,5,
    6,6,6,6,6,6,6,6,6,6,6,6,6};

__constant__ float c_bal[NSH] = {
    0.0f,
    0.05555555556f,0.05555555556f,0.05555555556f,
    0.03333333333f,0.03333333333f,0.03333333333f,0.03333333333f,0.03333333333f,
    0.02380952381f,0.02380952381f,0.02380952381f,0.02380952381f,0.02380952381f,0.02380952381f,0.02380952381f,
    0.01851851852f,0.01851851852f,0.01851851852f,0.01851851852f,0.01851851852f,0.01851851852f,0.01851851852f,0.01851851852f,0.01851851852f,
    0.01515151515f,0.01515151515f,0.01515151515f,0.01515151515f,0.01515151515f,0.01515151515f,0.01515151515f,0.01515151515f,0.01515151515f,0.01515151515f,0.01515151515f,
    0.01282051282f,0.01282051282f,0.01282051282f,0.01282051282f,0.01282051282f,0.01282051282f,0.01282051282f,0.01282051282f,0.01282051282f,0.01282051282f,0.01282051282f,0.01282051282f,0.01282051282f};

__device__ __forceinline__ float fast_silu(float v) {
    return __fdividef(v, 1.0f + __expf(-v));
}

// dot over K=128: thread owns one weight column (pad-stride), CNT activation rows.
template<int CNT>
__device__ __forceinline__ void dotc(const float* __restrict__ wcol,
                                     const float* __restrict__ xbase,
                                     int xstride, float* __restrict__ acc)
{
    #pragma unroll 2
    for (int c4 = 0; c4 < CC; c4 += 4) {
        float4 w = *reinterpret_cast<const float4*>(wcol + c4);
        #pragma unroll
        for (int k = 0; k < CNT; k++) {
            float4 xv = *reinterpret_cast<const float4*>(xbase + k * xstride + c4);
            acc[k] = fmaf(w.x, xv.x, acc[k]);
            acc[k] = fmaf(w.y, xv.y, acc[k]);
            acc[k] = fmaf(w.z, xv.z, acc[k]);
            acc[k] = fmaf(w.w, xv.w, acc[k]);
        }
    }
}

__device__ __forceinline__ void dotc_dispatch(int g, const float* wcol,
                                              const float* xbase, int xstride,
                                              float* acc)
{
    switch (g) {
        case 1:  dotc<1>(wcol, xbase, xstride, acc);  break;
        case 3:  dotc<3>(wcol, xbase, xstride, acc);  break;
        case 5:  dotc<5>(wcol, xbase, xstride, acc);  break;
        case 7:  dotc<7>(wcol, xbase, xstride, acc);  break;
        case 9:  dotc<9>(wcol, xbase, xstride, acc);  break;
        case 11: dotc<11>(wcol, xbase, xstride, acc); break;
        case 13: dotc<13>(wcol, xbase, xstride, acc); break;
        default: break;
    }
}

// Grid forward: i blocked by 4, tg loaded as float4 broadcast.
template<int KC>
__device__ __forceinline__ void fwd_grid(const float* __restrict__ hb,
                                         const float* __restrict__ tg,
                                         int psel, int o4, float4* __restrict__ acc)
{
    #pragma unroll 1
    for (int i4 = 0; i4 < HPAD; i4 += 4) {
        float4 h0 = *reinterpret_cast<const float4*>(hb + (i4 + 0) * HH + o4);
        float4 h1 = *reinterpret_cast<const float4*>(hb + (i4 + 1) * HH + o4);
        float4 h2 = *reinterpret_cast<const float4*>(hb + (i4 + 2) * HH + o4);
        float4 h3 = *reinterpret_cast<const float4*>(hb + (i4 + 3) * HH + o4);
        #pragma unroll
        for (int k = 0; k < KC; k++) {
            float4 t = *reinterpret_cast<const float4*>(tg + (psel + 4 * k) * TGS + i4);
            acc[k].x = fmaf(t.x, h0.x, acc[k].x);
            acc[k].y = fmaf(t.x, h0.y, acc[k].y);
            acc[k].z = fmaf(t.x, h0.z, acc[k].z);
            acc[k].w = fmaf(t.x, h0.w, acc[k].w);
            acc[k].x = fmaf(t.y, h1.x, acc[k].x);
            acc[k].y = fmaf(t.y, h1.y, acc[k].y);
            acc[k].z = fmaf(t.y, h1.z, acc[k].z);
            acc[k].w = fmaf(t.y, h1.w, acc[k].w);
            acc[k].x = fmaf(t.z, h2.x, acc[k].x);
            acc[k].y = fmaf(t.z, h2.y, acc[k].y);
            acc[k].z = fmaf(t.z, h2.z, acc[k].z);
            acc[k].w = fmaf(t.z, h2.w, acc[k].w);
            acc[k].x = fmaf(t.w, h3.x, acc[k].x);
            acc[k].y = fmaf(t.w, h3.y, acc[k].y);
            acc[k].z = fmaf(t.w, h3.z, acc[k].z);
            acc[k].w = fmaf(t.w, h3.w, acc[k].w);
        }
    }
}

// Grid backward: thread owns o4, KI rows i = isel+4k; acc persists across chunks.
template<int KI>
__device__ __forceinline__ void bwd_grid(const float* __restrict__ gb,
                                         const float* __restrict__ fgT,
                                         int isel, int o4, float4* __restrict__ acc)
{
    #pragma unroll 1
    for (int pb = 0; pb < PPAD; pb += 4) {
        float4 g0 = *reinterpret_cast<const float4*>(gb + (pb + 0) * HH + o4);
        float4 g1 = *reinterpret_cast<const float4*>(gb + (pb + 1) * HH + o4);
        float4 g2 = *reinterpret_cast<const float4*>(gb + (pb + 2) * HH + o4);
        float4 g3 = *reinterpret_cast<const float4*>(gb + (pb + 3) * HH + o4);
        #pragma unroll
        for (int k = 0; k < KI; k++) {
            float4 f = *reinterpret_cast<const float4*>(fgT + (isel + 4 * k) * PPAD + pb);
            acc[k].x = fmaf(f.x, g0.x, acc[k].x);
            acc[k].y = fmaf(f.x, g0.y, acc[k].y);
            acc[k].z = fmaf(f.x, g0.z, acc[k].z);
            acc[k].w = fmaf(f.x, g0.w, acc[k].w);
            acc[k].x = fmaf(f.y, g1.x, acc[k].x);
            acc[k].y = fmaf(f.y, g1.y, acc[k].y);
            acc[k].z = fmaf(f.y, g1.z, acc[k].z);
            acc[k].w = fmaf(f.y, g1.w, acc[k].w);
            acc[k].x = fmaf(f.z, g2.x, acc[k].x);
            acc[k].y = fmaf(f.z, g2.y, acc[k].y);
            acc[k].z = fmaf(f.z, g2.z, acc[k].z);
            acc[k].w = fmaf(f.z, g2.w, acc[k].w);
            acc[k].x = fmaf(f.w, g3.x, acc[k].x);
            acc[k].y = fmaf(f.w, g3.y, acc[k].y);
            acc[k].z = fmaf(f.w, g3.z, acc[k].z);
            acc[k].w = fmaf(f.w, g3.w, acc[k].w);
        }
    }
}

__global__ void __launch_bounds__(256, 1)
ffn_fused(const float* __restrict__ x,
          const float* __restrict__ ln0_w, const float* __restrict__ ln0_b,
          const float* __restrict__ aff_w,
          const float* __restrict__ w1, const float* __restrict__ b1,
          const float* __restrict__ gate_w, const float* __restrict__ gate_b,
          const float* __restrict__ w2, const float* __restrict__ b2,
          const float* __restrict__ to_grid, const float* __restrict__ from_grid,
          float* __restrict__ out)
{
    extern __shared__ float sm[];
    float* xn    = sm + O_XN;
    float* hbuf  = sm + O_HBUF;
    float* S     = sm + O_S;
    float* sgate = sm + O_SGATE;
    float* rbuf  = sm + O_RBUF;

    const int tid = threadIdx.x;
    const int n   = blockIdx.x;
    const int wid = tid >> 5;
    const int lid = tid & 31;

    // ---------------- Phase A: load + norms ----------------
    const float4* xin = reinterpret_cast<const float4*>(x + (size_t)n * (NSH * CC));
    float4* xns = reinterpret_cast<float4*>(xn);
    #pragma unroll 4
    for (int j4 = tid; j4 < NSH * CC / 4; j4 += 256) xns[j4] = xin[j4];
    __syncthreads();

    float s0 = 0.f, q0 = 0.f, sw = 0.f;
    #pragma unroll 4
    for (int j4 = tid; j4 < NSH * CC / 4; j4 += 256) {
        float4 v = xns[j4];
        int m = j4 >> 5;
        float d = v.x * v.x + v.y * v.y + v.z * v.z + v.w * v.w;
        if (m == 0) { s0 += v.x + v.y + v.z + v.w; q0 += d; }
        else        sw += c_bal[m] * d;
    }
    #pragma unroll
    for (int o = 16; o > 0; o >>= 1) {
        s0 += __shfl_xor_sync(0xffffffffu, s0, o);
        q0 += __shfl_xor_sync(0xffffffffu, q0, o);
        sw += __shfl_xor_sync(0xffffffffu, sw, o);
    }
    if (lid == 0) { rbuf[wid] = s0; rbuf[8 + wid] = q0; rbuf[16 + wid] = sw; }
    __syncthreads();
    if (tid == 0) {
        float a = 0.f, b = 0.f, c = 0.f;
        #pragma unroll
        for (int k = 0; k < 8; k++) { a += rbuf[k]; b += rbuf[8 + k]; c += rbuf[16 + k]; }
        float muv  = a * (1.0f / CC);
        float varv = b * (1.0f / CC) - muv * muv;
        rbuf[24] = muv;
        rbuf[25] = rsqrtf(varv + EPSV);
        rbuf[26] = rsqrtf(c * (1.0f / CC) + EPSV);
    }
    __syncthreads();
    const float mu = rbuf[24], rstd = rbuf[25], inv = rbuf[26];

    #pragma unroll 4
    for (int j4 = tid; j4 < NSH * CC / 4; j4 += 256) {
        int m = j4 >> 5, c4 = (j4 & 31) << 2;
        float4 v = xns[j4];
        if (m == 0) {
            float4 w = *reinterpret_cast<const float4*>(ln0_w + c4);
            float4 b = *reinterpret_cast<const float4*>(ln0_b + c4);
            v.x = (v.x - mu) * rstd * w.x + b.x;
            v.y = (v.y - mu) * rstd * w.y + b.y;
            v.z = (v.z - mu) * rstd * w.z + b.z;
            v.w = (v.w - mu) * rstd * w.w + b.w;
        } else {
            float4 a = *reinterpret_cast<const float4*>(aff_w + (c_ltab[m] - 1) * CC + c4);
            v.x *= inv * a.x; v.y *= inv * a.y; v.z *= inv * a.z; v.w *= inv * a.w;
        }
        xns[j4] = v;
    }
    __syncthreads();

    // ---------------- Phase B: gate = silu(xn0 @ gate_w^T + gate_b) ----------------
    {
        const int c4 = lid << 2;
        float4 x0 = *reinterpret_cast<const float4*>(xn + c4);
        for (int ho = wid; ho < HH; ho += 8) {
            float4 g = *reinterpret_cast<const float4*>(gate_w + ho * CC + c4);
            float p = g.x * x0.x + g.y * x0.y + g.z * x0.z + g.w * x0.w;
            #pragma unroll
            for (int o = 16; o > 0; o >>= 1) p += __shfl_xor_sync(0xffffffffu, p, o);
            if (lid == 0) sgate[ho] = fast_silu(p + gate_b[ho]);
        }
    }

    // ---------------- Phase C: h[m,:] = xn[m,:] @ w1[l]^T, single pass over 256 cols ----------------
    // thread owns H-column och = tid; all g rows register-blocked.
    {
        const int och = tid;
        float* wstC = S;
        for (int l = 0; l <= 6; l++) {
            const int g = 2 * l + 1, mbase = l * l;
            __syncthreads();   // protect wstC from previous readers
            const float4* wsrc = reinterpret_cast<const float4*>(w1 + (size_t)l * HH * CC);
            #pragma unroll 4
            for (int j4 = tid; j4 < HH * CC / 4; j4 += 256) {
                int o = j4 >> 5, c4 = (j4 & 31) << 2;
                *reinterpret_cast<float4*>(wstC + o * WCPAD + c4) = wsrc[j4];
            }
            __syncthreads();
            float acc[13];
            #pragma unroll
            for (int k = 0; k < 13; k++) acc[k] = 0.f;
            dotc_dispatch(g, wstC + och * WCPAD, xn + mbase * CC, CC, acc);
            #pragma unroll
            for (int k = 0; k < 13; k++) {
                if (k < g) {
                    float v = acc[k];
                    if (l == 0) v += b1[och];
                    hbuf[(mbase + k) * HH + och] = v;
                }
            }
        }
    }
    // zero hbuf pad rows 49..51
    for (int j = tid; j < 3 * HH; j += 256) hbuf[NSH * HH + j] = 0.f;
    __syncthreads();   // C compute done reading wstC, hbuf complete

    // ---------------- Phase D: ht = from_grid^T @ silu(to_grid @ h) ----------------
    float* gbuf = S;
    float* tgc  = S + 7168;
    float* fgcT = S + 8520;
    const int o4   = (tid & 63) << 2;
    const int psel = tid >> 6;             // also isel for backward
    // zero pads once
    for (int j = tid; j < 2 * HH; j += 256) gbuf[26 * HH + j] = 0.f;
    for (int j = tid; j < 26 * 3; j += 256) {
        int p = j / 3, c = j - p * 3;
        tgc[p * TGS + NSH + c] = 0.f;
    }
    for (int i = tid; i < NSH; i += 256) {
        fgcT[i * PPAD + 26] = 0.f; fgcT[i * PPAD + 27] = 0.f;
    }

    const int KI = (psel == 0) ? 13 : 12;  // i = psel + 4k
    float4 hacc[13];
    #pragma unroll
    for (int k = 0; k < 13; k++) hacc[k] = make_float4(0.f, 0.f, 0.f, 0.f);

    for (int ch = 0; ch < 7; ch++) {
        const int pbase = ch * 26;
        __syncthreads();   // prev chunk's bwd reads of gbuf/fgcT done (or pad-zero init)
        #pragma unroll 2
        for (int j = tid; j < 26 * NSH; j += 256) {
            int p = j / NSH, i = j - p * NSH;
            float tv = to_grid[(size_t)(pbase + p) * NSH + i];
            float fv = from_grid[(size_t)(pbase + p) * NSH + i];
            tgc[p * TGS + i] = tv;
            fgcT[i * PPAD + p] = fv;
        }
        __syncthreads();
        {
            float4 acc[7];
            const int kcnt = (psel < 2) ? 7 : 6;
            #pragma unroll
            for (int k = 0; k < 7; k++) acc[k] = make_float4(0.f, 0.f, 0.f, 0.f);
            if (psel < 2) fwd_grid<7>(hbuf, tgc, psel, o4, acc);
            else          fwd_grid<6>(hbuf, tgc, psel, o4, acc);
            #pragma unroll
            for (int k = 0; k < 7; k++) {
                if (k < kcnt) {
                    float4 v = acc[k];
                    v.x = fast_silu(v.x); v.y = fast_silu(v.y);
                    v.z = fast_silu(v.z); v.w = fast_silu(v.w);
                    *reinterpret_cast<float4*>(gbuf + (psel + 4 * k) * HH + o4) = v;
                }
            }
        }
        __syncthreads();   // gbuf complete (also: all fwd reads of hbuf done)
        if (psel == 0) bwd_grid<13>(gbuf, fgcT, psel, o4, hacc);
        else           bwd_grid<12>(gbuf, fgcT, psel, o4, hacc);
    }
    // ht retires into the (now dead) hbuf region
    float* htbf = hbuf;
    #pragma unroll
    for (int k = 0; k < 13; k++) {
        if (k < KI)
            *reinterpret_cast<float4*>(htbf + (psel + 4 * k) * HH + o4) = hacc[k];
    }

    // ---------------- Phase E: out[m,:] = h2[m,:] @ w2[l]^T (+b2 on m==0) ----------------
    // thread owns (out-col oc, K-half kh); whole w2[l] staged once; smem reduction.
    {
        float* wstE  = S;
        float* redn  = xn;    // xn dead after C
        float* outn  = out + (size_t)n * (NSH * CC);
        const int oc = tid & 127;
        const int kh = tid >> 7;
        for (int l = 0; l <= 6; l++) {
            const int g = 2 * l + 1, mbase = l * l;
            __syncthreads();   // protect wstE (bwd gbuf reads / prev compute) + redn
            const float4* wsrc = reinterpret_cast<const float4*>(w2 + (size_t)l * CC * HH);
            #pragma unroll 4
            for (int j4 = tid; j4 < CC * HH / 4; j4 += 256) {
                int o = j4 >> 6, i4 = (j4 & 63) << 2;
                *reinterpret_cast<float4*>(wstE + o * WEPAD + i4) = wsrc[j4];
            }
            __syncthreads();
            float acc[13];
            #pragma unroll
            for (int k = 0; k < 13; k++) acc[k] = 0.f;
            const float* xr = (l == 0) ? (sgate + kh * 128)
                                       : (htbf + mbase * HH + kh * 128);
            dotc_dispatch(g, wstE + oc * WEPAD + kh * 128, xr, HH, acc);
            if (kh == 1) {
                #pragma unroll
                for (int k = 0; k < 13; k++)
                    if (k < g) redn[k * 128 + oc] = acc[k];
            }
            __syncthreads();
            if (kh == 0) {
                #pragma unroll
                for (int k = 0; k < 13; k++) {
                    if (k < g) {
                        float v = acc[k] + redn[k * 128 + oc];
                        if (l == 0) v += b2[oc];
                        outn[(mbase + k) * CC + oc] = v;
                    }
                }
            }
        }
    }
}

extern "C" void kernel_launch(void* const* d_in, const int* in_sizes, int n_in,
                              void* d_out, int out_size)
{
    const float* x      = (const float*)d_in[0];
    const float* ln0_w  = (const float*)d_in[1];
    const float* ln0_b  = (const float*)d_in[2];
    const float* aff_w  = (const float*)d_in[3];
    const float* w1     = (const float*)d_in[4];
    const float* b1     = (const float*)d_in[5];
    const float* gate_w = (const float*)d_in[6];
    const float* gate_b = (const float*)d_in[7];
    const float* w2     = (const float*)d_in[8];
    const float* b2     = (const float*)d_in[9];
    const float* tg     = (const float*)d_in[10];
    const float* fg     = (const float*)d_in[11];
    float* out = (float*)d_out;

    const int n_nodes = in_sizes[0] / (NSH * CC);
    const int smem_bytes = SMEM_FLOATS * (int)sizeof(float);
    cudaFuncSetAttribute(ffn_fused, cudaFuncAttributeMaxDynamicSharedMemorySize, smem_bytes);
    ffn_fused<<<n_nodes, 256, smem_bytes>>>(x, ln0_w, ln0_b, aff_w, w1, b1,
                                            gate_w, gate_b, w2, b2, tg, fg, out);
}